// round 2
// baseline (speedup 1.0000x reference)
#include <cuda_runtime.h>
#include <math.h>

#define BATCH 8
#define NCLS 80
#define POOL 3320           // 1000+1000+1000+256+64
#define SCR_STRIDE 21504    // 16384+4096+1024
#define NEGV -1000000000.0f
#define MIN_SCORE 0.05f
#define NMS_THR 0.6f

// ---------------- device scratch (no runtime allocation allowed) ----------------
__device__ float  g_scr_scores[BATCH * SCR_STRIDE];
__device__ int    g_scr_class [BATCH * SCR_STRIDE];
__device__ float4 g_scr_boxes [BATCH * SCR_STRIDE];

__device__ float  g_pool_scores[BATCH * POOL];
__device__ int    g_pool_class [BATCH * POOL];
__device__ float4 g_pool_boxes [BATCH * POOL];

__device__ __forceinline__ float sigm(float x) { return 1.0f / (1.0f + expf(-x)); }

// ---------------- kernel A: per-location decode (one warp per location) --------
__global__ __launch_bounds__(256)
void decode_kernel(const float* __restrict__ cls,
                   const float* __restrict__ reg,
                   const float* __restrict__ ctr,
                   int W, float stride, int N,
                   int out_stride, int out_off, int to_pool)
{
    int gw   = (blockIdx.x * blockDim.x + threadIdx.x) >> 5;
    int lane = threadIdx.x & 31;
    if (gw >= BATCH * N) return;
    int b = gw / N;
    int k = gw - b * N;

    const float* cp = cls + (size_t)(b * N + k) * NCLS;
    float v = -3.4e38f; int ci = 0;
    #pragma unroll
    for (int c = lane; c < NCLS; c += 32) {
        float x = cp[c];
        if (x > v) { v = x; ci = c; }     // ascending c -> lowest class kept on tie
    }
    #pragma unroll
    for (int off = 16; off > 0; off >>= 1) {
        float ov = __shfl_down_sync(0xffffffffu, v, off);
        int   oi = __shfl_down_sync(0xffffffffu, ci, off);
        if (ov > v || (ov == v && oi < ci)) { v = ov; ci = oi; }
    }

    if (lane == 0) {
        float ct    = ctr[(size_t)b * N + k];
        float score = sqrtf(sigm(v) * sigm(ct));

        const float4 r = reinterpret_cast<const float4*>(reg)[(size_t)b * N + k];
        float e0 = expf(r.x), e1 = expf(r.y), e2 = expf(r.z), e3 = expf(r.w);

        // pos: x from inner spatial index (k % W), y from outer (k / W)
        float px = ((k % W) + 0.5f) * stride;
        float py = ((k / W) + 0.5f) * stride;

        int x1 = (int)(px - e0);          // C truncation == jnp astype(int32)
        int y1 = (int)(py - e1);
        int x2 = (int)(px + e2);
        int y2 = (int)(py + e3);
        x1 = max(x1, 0);    y1 = max(y1, 0);
        x2 = min(x2, 1023); y2 = min(y2, 1023);

        size_t o = (size_t)b * out_stride + out_off + k;
        if (to_pool) {
            g_pool_scores[o] = score;
            g_pool_class [o] = ci;
            g_pool_boxes [o] = make_float4((float)x1, (float)y1, (float)x2, (float)y2);
        } else {
            g_scr_scores[o] = score;
            g_scr_class [o] = ci;
            g_scr_boxes [o] = make_float4((float)x1, (float)y1, (float)x2, (float)y2);
        }
    }
}

// ---------------- kernel B: exact top-1000 per (batch, level 0..2) -------------
__global__ __launch_bounds__(1024)
void topk_kernel()
{
    const int lvlN[3]    = {16384, 4096, 1024};
    const int lvlOff[3]  = {0, 16384, 20480};
    const int poolOff[3] = {0, 1000, 2000};

    int b = blockIdx.x / 3;
    int l = blockIdx.x % 3;
    int N = lvlN[l];
    size_t base  = (size_t)b * SCR_STRIDE + lvlOff[l];
    size_t pbase = (size_t)b * POOL + poolOff[l];

    extern __shared__ unsigned sb[];                    // N score bit patterns
    __shared__ unsigned s_lo, s_hi, s_mid;
    __shared__ int s_cnt, s_w, s_t;
    __shared__ int tie[1024];

    int tid = threadIdx.x, nt = blockDim.x;

    for (int i = tid; i < N; i += nt)
        sb[i] = __float_as_uint(g_scr_scores[base + i]);  // scores >= 0: uint order == float order
    for (int i = tid; i < 1000; i += nt)
        g_pool_scores[pbase + i] = NEGV;                  // safe default for any unfilled slot
    if (tid == 0) { s_lo = 0u; s_hi = 0xffffffffu; }
    __syncthreads();

    // binary search for T = value of the 1000th largest (count_ge(T) >= 1000, count_ge(T+1) < 1000)
    for (int it = 0; it < 32; ++it) {
        if (tid == 0) {
            unsigned d = s_hi - s_lo;
            s_mid = s_lo + (d >> 1) + (d & 1u);           // ceil midpoint -> progress
            s_cnt = 0;
        }
        __syncthreads();
        if (s_lo < s_hi) {
            unsigned mid = s_mid;
            int loc = 0;
            for (int i = tid; i < N; i += nt) loc += (sb[i] >= mid);
            #pragma unroll
            for (int off = 16; off > 0; off >>= 1)
                loc += __shfl_down_sync(0xffffffffu, loc, off);
            if ((tid & 31) == 0 && loc) atomicAdd(&s_cnt, loc);
            __syncthreads();
            if (tid == 0) {
                if (s_cnt >= 1000) s_lo = s_mid; else s_hi = s_mid - 1u;
            }
        }
        __syncthreads();
    }
    unsigned T = s_lo;

    if (tid == 0) { s_w = 0; s_t = 0; }
    __syncthreads();

    // all strictly-greater candidates go in; ties collected
    for (int i = tid; i < N; i += nt) {
        unsigned x = sb[i];
        if (x > T) {
            int slot = atomicAdd(&s_w, 1);
            g_pool_scores[pbase + slot] = g_scr_scores[base + i];
            g_pool_class [pbase + slot] = g_scr_class [base + i];
            g_pool_boxes [pbase + slot] = g_scr_boxes [base + i];
        } else if (x == T) {
            int p = atomicAdd(&s_t, 1);
            if (p < 1024) tie[p] = i;
        }
    }
    __syncthreads();

    // fill remaining slots with lowest-index ties (jax.lax.top_k tie semantics)
    if (tid == 0) {
        int m    = s_w;
        int need = 1000 - m;
        int e    = min(s_t, 1024);
        for (int j = 0; j < need && j < e; ++j) {
            int bi = j;
            for (int q = j + 1; q < e; ++q) if (tie[q] < tie[bi]) bi = q;
            int tmp = tie[j]; tie[j] = tie[bi]; tie[bi] = tmp;
            int i = tie[j];
            int slot = m + j;
            g_pool_scores[pbase + slot] = g_scr_scores[base + i];
            g_pool_class [pbase + slot] = g_scr_class [base + i];
            g_pool_boxes [pbase + slot] = g_scr_boxes [base + i];
        }
    }
}

// ---------------- kernel C: greedy NMS, one block per image --------------------
#define NMS_NT 256
__global__ __launch_bounds__(NMS_NT)
void nms_kernel(float* __restrict__ out)
{
    int b = blockIdx.x;
    __shared__ float s[POOL];
    __shared__ short bx1[POOL], by1[POOL], bx2[POOL], by2[POOL];
    __shared__ float wv[NMS_NT / 32];
    __shared__ int   wi[NMS_NT / 32];
    __shared__ int s_sel, s_done;

    int tid = threadIdx.x;
    for (int i = tid; i < POOL; i += NMS_NT) {
        float sc = g_pool_scores[(size_t)b * POOL + i];
        s[i] = (sc > MIN_SCORE) ? sc : NEGV;
        float4 f = g_pool_boxes[(size_t)b * POOL + i];
        bx1[i] = (short)f.x; by1[i] = (short)f.y;
        bx2[i] = (short)f.z; by2[i] = (short)f.w;
    }
    if (tid == 0) s_done = 0;
    __syncthreads();

    float* out_s = out;            // (8,100)
    float* out_c = out + 800;      // (8,100)
    float* out_b = out + 1600;     // (8,100,4)

    for (int it = 0; it < 100; ++it) {
        if (s_done) {
            if (tid == 0) {
                out_s[b * 100 + it] = -1.f;
                out_c[b * 100 + it] = -1.f;
                float* ob = out_b + ((size_t)b * 100 + it) * 4;
                ob[0] = ob[1] = ob[2] = ob[3] = -1.f;
            }
            continue;
        }
        // block argmax, tie -> lowest index (jnp.argmax semantics)
        float bv = -2e9f; int bi = 0;
        for (int j = tid; j < POOL; j += NMS_NT) {
            float v = s[j];
            if (v > bv) { bv = v; bi = j; }
        }
        #pragma unroll
        for (int off = 16; off > 0; off >>= 1) {
            float ov = __shfl_down_sync(0xffffffffu, bv, off);
            int   oi = __shfl_down_sync(0xffffffffu, bi, off);
            if (ov > bv || (ov == bv && oi < bi)) { bv = ov; bi = oi; }
        }
        if ((tid & 31) == 0) { wv[tid >> 5] = bv; wi[tid >> 5] = bi; }
        __syncthreads();
        if (tid == 0) {
            float v = wv[0]; int ix = wi[0];
            #pragma unroll
            for (int w = 1; w < NMS_NT / 32; ++w)
                if (wv[w] > v || (wv[w] == v && wi[w] < ix)) { v = wv[w]; ix = wi[w]; }
            bool ok = v > MIN_SCORE;
            out_s[b * 100 + it] = ok ? v : -1.f;
            out_c[b * 100 + it] = ok ? (float)g_pool_class[(size_t)b * POOL + ix] : -1.f;
            float* ob = out_b + ((size_t)b * 100 + it) * 4;
            if (ok) { ob[0] = bx1[ix]; ob[1] = by1[ix]; ob[2] = bx2[ix]; ob[3] = by2[ix]; }
            else    { ob[0] = ob[1] = ob[2] = ob[3] = -1.f; }
            s[ix] = NEGV;
            s_sel = ok ? ix : -1;
            if (!ok) s_done = 1;
        }
        __syncthreads();
        int sel = s_sel;
        if (sel >= 0) {
            float rx1 = bx1[sel], ry1 = by1[sel], rx2 = bx2[sel], ry2 = by2[sel];
            float ra  = (rx2 - rx1) * (ry2 - ry1);
            for (int j = tid; j < POOL; j += NMS_NT) {
                float x1 = bx1[j], y1 = by1[j], x2 = bx2[j], y2 = by2[j];
                float iw = fmaxf(fminf(x2, rx2) - fmaxf(x1, rx1), 0.f);
                float ih = fmaxf(fminf(y2, ry2) - fmaxf(y1, ry1), 0.f);
                float inter = iw * ih;
                float a = (x2 - x1) * (y2 - y1);
                float iou = inter / (a + ra - inter + 1e-12f);   // exact fp32, matches ref
                if (iou > NMS_THR) s[j] = NEGV;
            }
        }
        __syncthreads();
    }
}

// ---------------- host launcher -------------------------------------------------
extern "C" void kernel_launch(void* const* d_in, const int* in_sizes, int n_in,
                              void* d_out, int out_size)
{
    (void)n_in; (void)out_size;

    const float* cls[5]; const float* reg[5]; const float* ctr[5];
    // Two plausible input orders: grouped by head type (signature order) or
    // interleaved per level (dict insertion order). Disambiguate by size:
    // grouped -> in_sizes[1] == cls1 == 8*64*64*80.
    if (in_sizes[1] == 8 * 64 * 64 * NCLS) {
        for (int i = 0; i < 5; i++) {
            cls[i] = (const float*)d_in[i];
            reg[i] = (const float*)d_in[5 + i];
            ctr[i] = (const float*)d_in[10 + i];
        }
    } else {
        for (int i = 0; i < 5; i++) {
            cls[i] = (const float*)d_in[3 * i + 0];
            reg[i] = (const float*)d_in[3 * i + 1];
            ctr[i] = (const float*)d_in[3 * i + 2];
        }
    }

    const int   Ws[5]      = {128, 64, 32, 16, 8};
    const float strides[5] = {8.f, 16.f, 32.f, 64.f, 128.f};
    const int   scrOff[3]  = {0, 16384, 20480};
    const int   poolOff[2] = {3000, 3256};     // level 3, level 4 go straight to pool

    for (int l = 0; l < 5; ++l) {
        int W = Ws[l];
        int N = W * W;
        int blocks = (BATCH * N * 32 + 255) / 256;   // one warp per location
        if (l < 3) {
            decode_kernel<<<blocks, 256>>>(cls[l], reg[l], ctr[l], W, strides[l], N,
                                           SCR_STRIDE, scrOff[l], 0);
        } else {
            decode_kernel<<<blocks, 256>>>(cls[l], reg[l], ctr[l], W, strides[l], N,
                                           POOL, poolOff[l - 3], 1);
        }
    }

    cudaFuncSetAttribute(topk_kernel, cudaFuncAttributeMaxDynamicSharedMemorySize, 65536);
    topk_kernel<<<24, 1024, 65536>>>();

    nms_kernel<<<BATCH, NMS_NT>>>((float*)d_out);
}

// round 3
// speedup vs baseline: 1.2676x; 1.2676x over previous
#include <cuda_runtime.h>
#include <math.h>

#define BATCH 8
#define NCLS 80
#define POOL 3320           // 1000+1000+1000+256+64
#define SCR_STRIDE 21504    // 16384+4096+1024
#define NEGV -1000000000.0f
#define MIN_SCORE 0.05f
#define NMS_THR 0.6f
#define TOTAL_WARPS 174592  // 8*(16384+4096+1024+256+64)

// ---------------- device scratch (no runtime allocation allowed) ----------------
__device__ float  g_scr_scores[BATCH * SCR_STRIDE];
__device__ int    g_scr_class [BATCH * SCR_STRIDE];
__device__ float4 g_scr_boxes [BATCH * SCR_STRIDE];

__device__ float  g_pool_scores[BATCH * POOL];
__device__ int    g_pool_class [BATCH * POOL];
__device__ float4 g_pool_boxes [BATCH * POOL];

__device__ __forceinline__ float sigm(float x) { return 1.0f / (1.0f + expf(-x)); }

struct HeadPtrs {
    const float* cls[5];
    const float* reg[5];
    const float* ctr[5];
};

// ---------------- kernel A: fused decode, all 5 levels, one warp/location ------
__global__ __launch_bounds__(256)
void decode_all_kernel(HeadPtrs P)
{
    int gw   = blockIdx.x * 8 + (threadIdx.x >> 5);
    int lane = threadIdx.x & 31;
    if (gw >= TOTAL_WARPS) return;

    // level dispatch by cumulative warp ranges: 131072,32768,8192,2048,512
    int lvl, base, logN, logW; float stride;
    if      (gw < 131072) { lvl=0; base=0;      logN=14; logW=7; stride=8.f;   }
    else if (gw < 163840) { lvl=1; base=131072; logN=12; logW=6; stride=16.f;  }
    else if (gw < 172032) { lvl=2; base=163840; logN=10; logW=5; stride=32.f;  }
    else if (gw < 174080) { lvl=3; base=172032; logN=8;  logW=4; stride=64.f;  }
    else                  { lvl=4; base=174080; logN=6;  logW=3; stride=128.f; }

    int local = gw - base;
    int b = local >> logN;
    int k = local & ((1 << logN) - 1);
    int N = 1 << logN;
    int W = 1 << logW;

    const float* cp = P.cls[lvl] + (size_t)(b * N + k) * NCLS;
    float v = -3.4e38f; int ci = 0;
    #pragma unroll
    for (int c = lane; c < NCLS; c += 32) {
        float x = cp[c];
        if (x > v) { v = x; ci = c; }     // ascending c -> lowest class kept on tie
    }
    #pragma unroll
    for (int off = 16; off > 0; off >>= 1) {
        float ov = __shfl_down_sync(0xffffffffu, v, off);
        int   oi = __shfl_down_sync(0xffffffffu, ci, off);
        if (ov > v || (ov == v && oi < ci)) { v = ov; ci = oi; }
    }

    if (lane == 0) {
        float ct    = P.ctr[lvl][(size_t)b * N + k];
        float score = sqrtf(sigm(v) * sigm(ct));

        const float4 r = reinterpret_cast<const float4*>(P.reg[lvl])[(size_t)b * N + k];
        float e0 = expf(r.x), e1 = expf(r.y), e2 = expf(r.z), e3 = expf(r.w);

        float px = ((k & (W - 1)) + 0.5f) * stride;
        float py = ((k >> logW)  + 0.5f) * stride;

        int x1 = (int)(px - e0);          // C truncation == jnp astype(int32)
        int y1 = (int)(py - e1);
        int x2 = (int)(px + e2);
        int y2 = (int)(py + e3);
        x1 = max(x1, 0);    y1 = max(y1, 0);
        x2 = min(x2, 1023); y2 = min(y2, 1023);

        float4 box = make_float4((float)x1, (float)y1, (float)x2, (float)y2);
        if (lvl < 3) {
            const int scrOff[3] = {0, 16384, 20480};
            size_t o = (size_t)b * SCR_STRIDE + scrOff[lvl] + k;
            g_scr_scores[o] = score;
            g_scr_class [o] = ci;
            g_scr_boxes [o] = box;
        } else {
            const int poolOff[2] = {3000, 3256};
            size_t o = (size_t)b * POOL + poolOff[lvl - 3] + k;
            g_pool_scores[o] = score;
            g_pool_class [o] = ci;
            g_pool_boxes [o] = box;
        }
    }
}

// ---------------- kernel B: exact top-1000 per (batch, level 0..2) -------------
__global__ __launch_bounds__(1024)
void topk_kernel()
{
    const int lvlN[3]    = {16384, 4096, 1024};
    const int lvlOff[3]  = {0, 16384, 20480};
    const int poolOff[3] = {0, 1000, 2000};

    int b = blockIdx.x / 3;
    int l = blockIdx.x % 3;
    int N = lvlN[l];
    size_t base  = (size_t)b * SCR_STRIDE + lvlOff[l];
    size_t pbase = (size_t)b * POOL + poolOff[l];

    extern __shared__ unsigned sb[];                    // N score bit patterns
    __shared__ unsigned s_lo, s_hi, s_mid;
    __shared__ int wcnt[32];
    __shared__ int s_w, s_t;
    __shared__ int tie[256];

    int tid = threadIdx.x, nt = blockDim.x;
    int wid = tid >> 5, lane = tid & 31;

    for (int i = tid; i < N; i += nt)
        sb[i] = __float_as_uint(g_scr_scores[base + i]);  // scores > 0: uint order == float order
    for (int i = tid; i < 1000; i += nt)
        g_pool_scores[pbase + i] = NEGV;                  // safety default
    if (tid == 0) { s_lo = 0u; s_hi = 0xffffffffu; }
    __syncthreads();

    // binary search: invariant count_ge(lo) >= 1000, count_ge(hi+1) < 1000.
    // Converged iterations (lo==hi) are harmless no-ops.
    for (int it = 0; it < 32; ++it) {
        if (tid == 0) {
            unsigned d = s_hi - s_lo;
            s_mid = s_lo + (d >> 1) + (d & 1u);           // ceil midpoint -> progress
        }
        __syncthreads();
        unsigned mid = s_mid;
        int loc = 0;
        for (int i = tid; i < N; i += nt) loc += (sb[i] >= mid);
        #pragma unroll
        for (int off = 16; off > 0; off >>= 1)
            loc += __shfl_down_sync(0xffffffffu, loc, off);
        if (lane == 0) wcnt[wid] = loc;
        __syncthreads();
        if (tid < 32) {
            int v = wcnt[tid];
            #pragma unroll
            for (int off = 16; off > 0; off >>= 1)
                v += __shfl_down_sync(0xffffffffu, v, off);
            if (tid == 0) {
                if (v >= 1000) s_lo = s_mid; else s_hi = s_mid - 1u;
            }
        }
        __syncthreads();
    }
    unsigned T = s_lo;

    if (tid == 0) { s_w = 0; s_t = 0; }
    __syncthreads();

    // all strictly-greater candidates go in; ties collected (rare)
    for (int i = tid; i < N; i += nt) {
        unsigned x = sb[i];
        if (x > T) {
            int slot = atomicAdd(&s_w, 1);
            g_pool_scores[pbase + slot] = g_scr_scores[base + i];
            g_pool_class [pbase + slot] = g_scr_class [base + i];
            g_pool_boxes [pbase + slot] = g_scr_boxes [base + i];
        } else if (x == T) {
            int p = atomicAdd(&s_t, 1);
            if (p < 256) tie[p] = i;
        }
    }
    __syncthreads();

    // fill remaining slots with lowest-index ties (jax.lax.top_k tie semantics)
    if (tid == 0) {
        int m    = s_w;
        int need = 1000 - m;
        int e    = min(s_t, 256);
        for (int j = 0; j < need && j < e; ++j) {
            int bi = j;
            for (int q = j + 1; q < e; ++q) if (tie[q] < tie[bi]) bi = q;
            int tmp = tie[j]; tie[j] = tie[bi]; tie[bi] = tmp;
            int i = tie[j];
            int slot = m + j;
            g_pool_scores[pbase + slot] = g_scr_scores[base + i];
            g_pool_class [pbase + slot] = g_scr_class [base + i];
            g_pool_boxes [pbase + slot] = g_scr_boxes [base + i];
        }
    }
}

// ---------------- kernel C: sort + greedy sweep NMS, one block per image -------
#define NMS_NT 1024
#define NPAD 4096

__global__ __launch_bounds__(NMS_NT)
void nms_kernel(float* __restrict__ out)
{
    int b = blockIdx.x;
    extern __shared__ char dsm[];
    unsigned long long* key = (unsigned long long*)dsm;           // 4096*8  = 32768
    short* sx1  = (short*)(dsm + 32768);                          // 3328*2
    short* sy1  = (short*)(dsm + 32768 + 6656);
    short* sx2  = (short*)(dsm + 32768 + 13312);
    short* sy2  = (short*)(dsm + 32768 + 19968);                  // -> 59392
    short* scls = (short*)(dsm + 59392);                          // -> 66048
    float* ssc  = (float*)(dsm + 66048);                          // -> 79360
    unsigned char* sup = (unsigned char*)(dsm + 79360);           // -> 83456
    float* outb = (float*)(dsm + 83456);                          // 600 floats -> 85856

    __shared__ int wmin[32];
    __shared__ int s_sel;

    int tid = threadIdx.x;
    int wid = tid >> 5, lane = tid & 31;

    // 1. build sort keys: (score_bits << 32) | ~pool_index ; dead -> 0
    for (int i = tid; i < NPAD; i += NMS_NT) {
        unsigned long long k = 0ull;
        if (i < POOL) {
            float sc = g_pool_scores[(size_t)b * POOL + i];
            if (sc > MIN_SCORE)
                k = ((unsigned long long)__float_as_uint(sc) << 32) | (unsigned)(~i);
        }
        key[i] = k;
    }
    for (int i = tid; i < 600; i += NMS_NT) outb[i] = -1.f;

    // 2. bitonic sort, descending (score desc, pool index asc on equal scores)
    for (int kk = 2; kk <= NPAD; kk <<= 1) {
        for (int jj = kk >> 1; jj > 0; jj >>= 1) {
            __syncthreads();
            #pragma unroll
            for (int t = tid; t < NPAD; t += NMS_NT) {
                int ixj = t ^ jj;
                if (ixj > t) {
                    unsigned long long a = key[t], c = key[ixj];
                    bool up = ((t & kk) == 0);
                    if ((a < c) == up) { key[t] = c; key[ixj] = a; }
                }
            }
        }
    }
    __syncthreads();

    // 3. gather into sorted arrays
    for (int i = tid; i < POOL; i += NMS_NT) {
        unsigned long long k = key[i];
        if (k != 0ull) {
            unsigned idx  = ~(unsigned)(k & 0xffffffffull);
            unsigned bits = (unsigned)(k >> 32);
            ssc[i] = __uint_as_float(bits);
            float4 f = g_pool_boxes[(size_t)b * POOL + idx];
            sx1[i] = (short)f.x; sy1[i] = (short)f.y;
            sx2[i] = (short)f.z; sy2[i] = (short)f.w;
            scls[i] = (short)g_pool_class[(size_t)b * POOL + idx];
            sup[i] = 0;
        } else {
            sup[i] = 1;
        }
    }
    __syncthreads();

    // 4. greedy sweep: next selection == first alive entry in sorted order
    int cursor = 0;
    for (int it = 0; it < 100; ++it) {
        int sel = -1;
        while (cursor < POOL) {
            int i = cursor + tid;
            bool alive = (i < POOL) && (sup[i] == 0);
            unsigned m = __ballot_sync(0xffffffffu, alive);
            if (lane == 0) wmin[wid] = m ? (cursor + (wid << 5) + __ffs(m) - 1) : 0x7fffffff;
            __syncthreads();
            if (tid < 32) {
                int v = wmin[tid];
                #pragma unroll
                for (int off = 16; off > 0; off >>= 1)
                    v = min(v, __shfl_down_sync(0xffffffffu, v, off));
                if (tid == 0) s_sel = v;
            }
            __syncthreads();
            if (s_sel != 0x7fffffff) { sel = s_sel; break; }
            cursor += NMS_NT;
        }
        if (sel < 0) break;            // pool exhausted: rest of outb stays -1

        if (tid == 0) {
            outb[it * 6 + 0] = ssc[sel];
            outb[it * 6 + 1] = (float)scls[sel];
            outb[it * 6 + 2] = (float)sx1[sel];
            outb[it * 6 + 3] = (float)sy1[sel];
            outb[it * 6 + 4] = (float)sx2[sel];
            outb[it * 6 + 5] = (float)sy2[sel];
        }
        float rx1 = sx1[sel], ry1 = sy1[sel], rx2 = sx2[sel], ry2 = sy2[sel];
        float ra  = (rx2 - rx1) * (ry2 - ry1);
        for (int j = sel + 1 + tid; j < POOL; j += NMS_NT) {
            if (sup[j]) continue;
            float x1 = sx1[j], y1 = sy1[j], x2 = sx2[j], y2 = sy2[j];
            float iw = fmaxf(fminf(x2, rx2) - fmaxf(x1, rx1), 0.f);
            float ih = fmaxf(fminf(y2, ry2) - fmaxf(y1, ry1), 0.f);
            float inter = iw * ih;
            float a = (x2 - x1) * (y2 - y1);
            float denom = ((a + ra) - inter) + 1e-12f;    // same association as reference
            if (inter / denom > NMS_THR) sup[j] = 1;
        }
        cursor = sel + 1;
        __syncthreads();
    }
    __syncthreads();

    // 5. write outputs: scores (8,100), classes (8,100), boxes (8,100,4)
    if (tid < 100) {
        out[b * 100 + tid]       = outb[tid * 6 + 0];
        out[800 + b * 100 + tid] = outb[tid * 6 + 1];
        float* ob = out + 1600 + ((size_t)b * 100 + tid) * 4;
        ob[0] = outb[tid * 6 + 2];
        ob[1] = outb[tid * 6 + 3];
        ob[2] = outb[tid * 6 + 4];
        ob[3] = outb[tid * 6 + 5];
    }
}

// ---------------- host launcher -------------------------------------------------
extern "C" void kernel_launch(void* const* d_in, const int* in_sizes, int n_in,
                              void* d_out, int out_size)
{
    (void)n_in; (void)out_size;

    HeadPtrs P;
    if (in_sizes[1] == 8 * 64 * 64 * NCLS) {
        for (int i = 0; i < 5; i++) {
            P.cls[i] = (const float*)d_in[i];
            P.reg[i] = (const float*)d_in[5 + i];
            P.ctr[i] = (const float*)d_in[10 + i];
        }
    } else {
        for (int i = 0; i < 5; i++) {
            P.cls[i] = (const float*)d_in[3 * i + 0];
            P.reg[i] = (const float*)d_in[3 * i + 1];
            P.ctr[i] = (const float*)d_in[3 * i + 2];
        }
    }

    decode_all_kernel<<<TOTAL_WARPS / 8, 256>>>(P);

    cudaFuncSetAttribute(topk_kernel, cudaFuncAttributeMaxDynamicSharedMemorySize, 65536);
    topk_kernel<<<24, 1024, 65536>>>();

    cudaFuncSetAttribute(nms_kernel, cudaFuncAttributeMaxDynamicSharedMemorySize, 86016);
    nms_kernel<<<BATCH, NMS_NT, 86016>>>((float*)d_out);
}

// round 8
// speedup vs baseline: 1.9495x; 1.5379x over previous
#include <cuda_runtime.h>
#include <math.h>

#define BATCH 8
#define NCLS 80
#define POOL 3320           // 1000+1000+1000+256+64
#define NPAD 4096
#define SCR_STRIDE 21504    // 16384+4096+1024
#define NEGV -1000000000.0f
#define MIN_SCORE 0.05f
#define NMS_THR 0.6f
#define TOTAL_WARPS 174592  // 8*(16384+4096+1024+256+64)

// ---------------- device scratch ----------------
__device__ float  g_scr_scores[BATCH * SCR_STRIDE];
__device__ int    g_scr_class [BATCH * SCR_STRIDE];
__device__ float4 g_scr_boxes [BATCH * SCR_STRIDE];

__device__ float  g_pool_scores[BATCH * POOL];
__device__ int    g_pool_class [BATCH * POOL];
__device__ float4 g_pool_boxes [BATCH * POOL];

__device__ __forceinline__ float sigm(float x) { return 1.0f / (1.0f + expf(-x)); }

struct HeadPtrs {
    const float* cls[5];
    const float* reg[5];
    const float* ctr[5];
};

// ---------------- kernel A: fused decode, one warp per location ----------------
__global__ __launch_bounds__(256)
void decode_all_kernel(HeadPtrs P)
{
    int gw   = blockIdx.x * 8 + (threadIdx.x >> 5);
    int lane = threadIdx.x & 31;
    if (gw >= TOTAL_WARPS) return;

    int lvl, base, logN, logW; float stride;
    if      (gw < 131072) { lvl=0; base=0;      logN=14; logW=7; stride=8.f;   }
    else if (gw < 163840) { lvl=1; base=131072; logN=12; logW=6; stride=16.f;  }
    else if (gw < 172032) { lvl=2; base=163840; logN=10; logW=5; stride=32.f;  }
    else if (gw < 174080) { lvl=3; base=172032; logN=8;  logW=4; stride=64.f;  }
    else                  { lvl=4; base=174080; logN=6;  logW=3; stride=128.f; }

    int local = gw - base;
    int b = local >> logN;
    int k = local & ((1 << logN) - 1);
    int N = 1 << logN;

    // 80 classes = 20 float4; lanes 0..19 load one each (single LDG.128)
    const float4* cp4 = (const float4*)(P.cls[lvl] + (size_t)(b * N + k) * NCLS);
    float v = -3.4e38f; int ci = 0;
    if (lane < 20) {
        float4 q = cp4[lane];
        int c0 = lane * 4;
        v = q.x; ci = c0;
        if (q.y > v) { v = q.y; ci = c0 + 1; }   // strict > : lowest class on tie
        if (q.z > v) { v = q.z; ci = c0 + 2; }
        if (q.w > v) { v = q.w; ci = c0 + 3; }
    }
    // proven shfl reduction: max value, lowest class index on ties
    #pragma unroll
    for (int off = 16; off > 0; off >>= 1) {
        float ov = __shfl_down_sync(0xffffffffu, v, off);
        int   oi = __shfl_down_sync(0xffffffffu, ci, off);
        if (ov > v || (ov == v && oi < ci)) { v = ov; ci = oi; }
    }

    if (lane == 0) {
        float ct    = P.ctr[lvl][(size_t)b * N + k];
        float score = sqrtf(sigm(v) * sigm(ct));

        const float4 r = ((const float4*)P.reg[lvl])[(size_t)b * N + k];
        float e0 = expf(r.x), e1 = expf(r.y), e2 = expf(r.z), e3 = expf(r.w);

        float px = ((k & ((1 << logW) - 1)) + 0.5f) * stride;
        float py = ((k >> logW)             + 0.5f) * stride;

        int x1 = (int)(px - e0);          // C truncation == jnp astype(int32)
        int y1 = (int)(py - e1);
        int x2 = (int)(px + e2);
        int y2 = (int)(py + e3);
        x1 = max(x1, 0);    y1 = max(y1, 0);
        x2 = min(x2, 1023); y2 = min(y2, 1023);

        float4 box = make_float4((float)x1, (float)y1, (float)x2, (float)y2);
        if (lvl < 3) {
            const int scrOff[3] = {0, 16384, 20480};
            size_t o = (size_t)b * SCR_STRIDE + scrOff[lvl] + k;
            g_scr_scores[o] = score;
            g_scr_class [o] = ci;
            g_scr_boxes [o] = box;
        } else {
            const int poolOff[2] = {3000, 3256};
            size_t o = (size_t)b * POOL + poolOff[lvl - 3] + k;
            g_pool_scores[o] = score;
            g_pool_class [o] = ci;
            g_pool_boxes [o] = box;
        }
    }
}

// ---------------- kernel B: histogram radix-select top-1000 --------------------
#define TK_NT 512
__global__ __launch_bounds__(TK_NT)
void topk_kernel()
{
    const int lvlN[3]    = {16384, 4096, 1024};
    const int lvlOff[3]  = {0, 16384, 20480};
    const int poolOff[3] = {0, 1000, 2000};

    int b = blockIdx.x / 3;
    int l = blockIdx.x % 3;
    int N = lvlN[l];
    size_t base  = (size_t)b * SCR_STRIDE + lvlOff[l];
    size_t pbase = (size_t)b * POOL + poolOff[l];

    extern __shared__ char tsm[];
    int* hist = (int*)tsm;                                          // 8192*4 = 32768
    unsigned long long* stash = (unsigned long long*)(tsm + 32768); // 4096*8 = 32768
    __shared__ int wsum[16], wsuf[16];
    __shared__ int s_B, s_above, s_w, s_t;
    __shared__ unsigned s_T;

    int tid = threadIdx.x, lane = tid & 31, wid = tid >> 5;

    for (int i = tid; i < 8192; i += TK_NT) hist[i] = 0;
    for (int i = tid; i < 1000; i += TK_NT) g_pool_scores[pbase + i] = NEGV; // safety
    if (tid == 0) { s_w = 0; s_t = 0; }
    __syncthreads();

    // pass 1: histogram of bits>>17 (scores in (0,1) -> bins < 8128)
    for (int i = tid; i < N; i += TK_NT) {
        unsigned u = __float_as_uint(g_scr_scores[base + i]);
        atomicAdd(&hist[u >> 17], 1);
    }
    __syncthreads();

    // block suffix scan over bins: find bin B with above(B) < 1000 <= above(B)+hist[B]
    int lo_bin = tid * 16;
    int psum = 0;
    #pragma unroll
    for (int j = 0; j < 16; j++) psum += hist[lo_bin + j];
    int x = psum;                                   // warp inclusive suffix scan
    #pragma unroll
    for (int off = 1; off < 32; off <<= 1) {
        int y = __shfl_down_sync(0xffffffffu, x, off);
        if (lane + off < 32) x += y;
    }
    if (lane == 0) wsum[wid] = x;
    __syncthreads();
    if (tid < 16) {
        int y = wsum[tid];
        #pragma unroll
        for (int off = 1; off < 16; off <<= 1) {
            int z = __shfl_down_sync(0xffffu, y, off);
            if (tid + off < 16) y += z;
        }
        wsuf[tid] = y;
    }
    __syncthreads();
    {
        int higher = (wid + 1 < 16) ? wsuf[wid + 1] : 0;
        int cum = higher + (x - psum);              // count in bins above this range
        #pragma unroll
        for (int j = 15; j >= 0; j--) {
            int h = hist[lo_bin + j];
            if (cum < 1000 && cum + h >= 1000) { s_B = lo_bin + j; s_above = cum; }
            cum += h;
        }
    }
    __syncthreads();
    int B = s_B, above = s_above;

    // pass 2: bins > B emit (plain shared-atomic slots); bin == B stashed
    for (int i = tid; i < N; i += TK_NT) {
        unsigned u = __float_as_uint(g_scr_scores[base + i]);
        int bin = (int)(u >> 17);
        if (bin > B) {
            int slot = atomicAdd(&s_w, 1);
            g_pool_scores[pbase + slot] = __uint_as_float(u);
            g_pool_class [pbase + slot] = g_scr_class[base + i];
            g_pool_boxes [pbase + slot] = g_scr_boxes[base + i];
        } else if (bin == B) {
            int p = atomicAdd(&s_t, 1);
            if (p < 4096) stash[p] = ((unsigned long long)u << 32) | (unsigned)i;
        }
    }
    __syncthreads();

    int M = min(s_t, 4096);
    int kneed = 1000 - above;                // how many needed from bin B

    // warp 0: 17-bit binary search within bin for threshold T
    if (wid == 0) {
        unsigned lo = (unsigned)B << 17, hi = ((unsigned)B << 17) | 0x1FFFFu;
        for (int it = 0; it < 17; it++) {
            unsigned d   = hi - lo;
            unsigned mid = lo + (d >> 1) + (d & 1u);    // ceil midpoint
            int loc = 0;
            for (int i = lane; i < M; i += 32) loc += ((unsigned)(stash[i] >> 32) >= mid);
            #pragma unroll
            for (int off = 16; off > 0; off >>= 1)
                loc += __shfl_xor_sync(0xffffffffu, loc, off);   // all lanes get total
            if (lo < hi) {
                if (loc >= kneed) lo = mid; else hi = mid - 1u;
            }
        }
        if (lane == 0) s_T = lo;
    }
    __syncthreads();
    unsigned T = s_T;

    // emit stash strictly greater than T
    for (int i = tid; i < M; i += TK_NT) {
        if ((unsigned)(stash[i] >> 32) > T) {
            int slot = atomicAdd(&s_w, 1);
            unsigned idx = (unsigned)(stash[i] & 0xffffffffull);
            g_pool_scores[pbase + slot] = __uint_as_float((unsigned)(stash[i] >> 32));
            g_pool_class [pbase + slot] = g_scr_class[base + idx];
            g_pool_boxes [pbase + slot] = g_scr_boxes[base + idx];
        }
    }
    __syncthreads();

    // ties == T: lowest original indices first (jax.lax.top_k tie semantics); tiny
    if (tid == 0) {
        int got  = s_w;
        int need = 1000 - got;
        for (int j = 0; j < need; j++) {
            unsigned bestIdx = 0xffffffffu; int bestPos = -1;
            for (int i = 0; i < M; i++) {
                unsigned long long e = stash[i];
                if ((unsigned)(e >> 32) == T) {
                    unsigned ii = (unsigned)(e & 0xffffffffull);
                    if (ii < bestIdx) { bestIdx = ii; bestPos = i; }
                }
            }
            if (bestPos < 0) break;
            stash[bestPos] = 0;                    // consume
            int slot = got + j;
            g_pool_scores[pbase + slot] = __uint_as_float(T);
            g_pool_class [pbase + slot] = g_scr_class[base + bestIdx];
            g_pool_boxes [pbase + slot] = g_scr_boxes[base + bestIdx];
        }
    }
}

// ---------------- kernel C: sort + scan-kept NMS, one block per image ----------
#define NMS_NT 512
__global__ __launch_bounds__(NMS_NT)
void nms_kernel(float* __restrict__ out)
{
    int b = blockIdx.x;
    extern __shared__ char dsm[];
    unsigned long long* key = (unsigned long long*)dsm;   // 4096*8 = 32768
    short* sx1  = (short*)(dsm + 32768);                  // 3328*2 each
    short* sy1  = (short*)(dsm + 32768 + 6656);
    short* sx2  = (short*)(dsm + 32768 + 13312);
    short* sy2  = (short*)(dsm + 32768 + 19968);
    short* scls = (short*)(dsm + 32768 + 26624);          // -> 66048
    float* ssc  = (float*)(dsm + 66048);                  // 3328*4 -> 79360
    float* kx1  = (float*)(dsm + 79360);                  // kept arrays: 7*100 floats
    float* ky1  = kx1 + 100;
    float* kx2  = kx1 + 200;
    float* ky2  = kx1 + 300;
    float* kar  = kx1 + 400;
    float* ksc  = kx1 + 500;
    float* kcl  = kx1 + 600;                              // end 82160

    int tid = threadIdx.x, lane = tid & 31;

    // keys: (score_bits << 32) | ~pool_index ; dead -> 0
    for (int i = tid; i < NPAD; i += NMS_NT) {
        unsigned long long k = 0ull;
        if (i < POOL) {
            float sc = g_pool_scores[(size_t)b * POOL + i];
            if (sc > MIN_SCORE)
                k = ((unsigned long long)__float_as_uint(sc) << 32) | (unsigned)(~i);
        }
        key[i] = k;
    }

    // bitonic sort descending (score desc, pool index asc on equal scores)
    for (int kk = 2; kk <= NPAD; kk <<= 1) {
        for (int jj = kk >> 1; jj > 0; jj >>= 1) {
            __syncthreads();
            for (int t = tid; t < NPAD; t += NMS_NT) {
                int ixj = t ^ jj;
                if (ixj > t) {
                    unsigned long long a = key[t], c = key[ixj];
                    bool up = ((t & kk) == 0);
                    if ((a < c) == up) { key[t] = c; key[ixj] = a; }
                }
            }
        }
    }
    __syncthreads();

    // gather sorted candidates
    for (int i = tid; i < POOL; i += NMS_NT) {
        unsigned long long k = key[i];
        if (k) {
            unsigned idx = ~(unsigned)(k & 0xffffffffull);
            ssc[i] = __uint_as_float((unsigned)(k >> 32));
            float4 f = g_pool_boxes[(size_t)b * POOL + idx];
            sx1[i] = (short)f.x; sy1[i] = (short)f.y;
            sx2[i] = (short)f.z; sy2[i] = (short)f.w;
            scls[i] = (short)g_pool_class[(size_t)b * POOL + idx];
        } else {
            ssc[i] = 0.f;
        }
    }
    __syncthreads();

    // scan-kept greedy NMS: warp 0 only, broadcasts via shared + __syncwarp.
    // Equivalence: greedy argmax-NMS == scan sorted order, keep iff
    // IoU <= thr vs every previously-kept box (only kept boxes suppress).
    if (tid < 32) {
        int kept = 0;
        for (int base0 = 0; base0 < POOL && kept < 100; base0 += 32) {
            if (ssc[base0] <= 0.f) break;          // sorted: all dead from here
            int i = base0 + lane;
            bool alive = (i < POOL) && (ssc[i] > 0.f);
            float x1 = 0, y1 = 0, x2 = 0, y2 = 0, a = 0;
            if (alive) {
                x1 = sx1[i]; y1 = sy1[i]; x2 = sx2[i]; y2 = sy2[i];
                a = (x2 - x1) * (y2 - y1);
                #pragma unroll 1
                for (int k = 0; k < kept && alive; k++) {
                    float iw = fmaxf(fminf(x2, kx2[k]) - fmaxf(x1, kx1[k]), 0.f);
                    float ih = fmaxf(fminf(y2, ky2[k]) - fmaxf(y1, ky1[k]), 0.f);
                    float inter = iw * ih;
                    float denom = ((a + kar[k]) - inter) + 1e-12f;  // same assoc as ref
                    if (inter / denom > NMS_THR) alive = false;
                }
            }
            unsigned m = __ballot_sync(0xffffffffu, alive);
            while (m != 0u && kept < 100) {
                int sl = __ffs(m) - 1;
                if (lane == sl) {
                    kx1[kept] = x1; ky1[kept] = y1;
                    kx2[kept] = x2; ky2[kept] = y2;
                    kar[kept] = a;
                    ksc[kept] = ssc[i];
                    kcl[kept] = (float)scls[i];
                    alive = false;
                }
                __syncwarp();
                float rx1 = kx1[kept], ry1 = ky1[kept];
                float rx2 = kx2[kept], ry2 = ky2[kept], ra = kar[kept];
                kept++;
                if (alive && lane > sl) {
                    float iw = fmaxf(fminf(x2, rx2) - fmaxf(x1, rx1), 0.f);
                    float ih = fmaxf(fminf(y2, ry2) - fmaxf(y1, ry1), 0.f);
                    float inter = iw * ih;
                    float denom = ((a + ra) - inter) + 1e-12f;
                    if (inter / denom > NMS_THR) alive = false;
                }
                m = __ballot_sync(0xffffffffu, alive);
            }
        }
        // warp 0 owns ALL output writes (no cross-warp race)
        for (int j = lane; j < 100; j += 32) {
            bool ok = j < kept;
            out[b * 100 + j]       = ok ? ksc[j] : -1.f;
            out[800 + b * 100 + j] = ok ? kcl[j] : -1.f;
            float* ob = out + 1600 + ((size_t)(b * 100 + j)) * 4;
            if (ok) { ob[0] = kx1[j]; ob[1] = ky1[j]; ob[2] = kx2[j]; ob[3] = ky2[j]; }
            else    { ob[0] = ob[1] = ob[2] = ob[3] = -1.f; }
        }
    }
}

// ---------------- host launcher -------------------------------------------------
extern "C" void kernel_launch(void* const* d_in, const int* in_sizes, int n_in,
                              void* d_out, int out_size)
{
    (void)n_in; (void)out_size;

    HeadPtrs P;
    if (in_sizes[1] == 8 * 64 * 64 * NCLS) {
        for (int i = 0; i < 5; i++) {
            P.cls[i] = (const float*)d_in[i];
            P.reg[i] = (const float*)d_in[5 + i];
            P.ctr[i] = (const float*)d_in[10 + i];
        }
    } else {
        for (int i = 0; i < 5; i++) {
            P.cls[i] = (const float*)d_in[3 * i + 0];
            P.reg[i] = (const float*)d_in[3 * i + 1];
            P.ctr[i] = (const float*)d_in[3 * i + 2];
        }
    }

    decode_all_kernel<<<TOTAL_WARPS / 8, 256>>>(P);

    cudaFuncSetAttribute(topk_kernel, cudaFuncAttributeMaxDynamicSharedMemorySize, 65536);
    topk_kernel<<<24, TK_NT, 65536>>>();

    cudaFuncSetAttribute(nms_kernel, cudaFuncAttributeMaxDynamicSharedMemorySize, 82176);
    nms_kernel<<<BATCH, NMS_NT, 82176>>>((float*)d_out);
}

// round 9
// speedup vs baseline: 3.1632x; 1.6226x over previous
#include <cuda_runtime.h>
#include <math.h>

#define BATCH 8
#define NCLS 80
#define POOL 3320           // 1000+1000+1000+256+64
#define NPAD 4096
#define SCR_STRIDE 21504    // 16384+4096+1024
#define NEGV -1000000000.0f
#define MIN_SCORE 0.05f
#define NMS_THR 0.6f
#define TOTAL_LOCS 174592   // 8*(16384+4096+1024+256+64)

// ---------------- device scratch ----------------
__device__ float  g_scr_scores[BATCH * SCR_STRIDE];
__device__ int    g_scr_class [BATCH * SCR_STRIDE];
__device__ float4 g_scr_boxes [BATCH * SCR_STRIDE];

__device__ float  g_pool_scores[BATCH * POOL];
__device__ int    g_pool_class [BATCH * POOL];
__device__ float4 g_pool_boxes [BATCH * POOL];

__device__ __forceinline__ float sigm(float x) { return 1.0f / (1.0f + expf(-x)); }

struct HeadPtrs {
    const float* cls[5];
    const float* reg[5];
    const float* ctr[5];
};

// ---------------- kernel A: fused decode, ONE THREAD per location --------------
// All level boundaries (131072,163840,172032,174080) are multiples of 256, so a
// 256-thread block never straddles levels (no divergent dispatch inside a block).
__global__ __launch_bounds__(256)
void decode_all_kernel(HeadPtrs P)
{
    int t = blockIdx.x * 256 + threadIdx.x;
    if (t >= TOTAL_LOCS) return;

    int lvl, base, logN, logW; float stride;
    if      (t < 131072) { lvl=0; base=0;      logN=14; logW=7; stride=8.f;   }
    else if (t < 163840) { lvl=1; base=131072; logN=12; logW=6; stride=16.f;  }
    else if (t < 172032) { lvl=2; base=163840; logN=10; logW=5; stride=32.f;  }
    else if (t < 174080) { lvl=3; base=172032; logN=8;  logW=4; stride=64.f;  }
    else                 { lvl=4; base=174080; logN=6;  logW=3; stride=128.f; }

    int local = t - base;
    int b = local >> logN;
    int k = local & ((1 << logN) - 1);
    int N = 1 << logN;

    // 80 classes = 20 float4, read sequentially by this thread.
    // 4 independent accumulator chains (one per component) keep ILP high;
    // strict > with ascending class index == lowest class on ties.
    const float4* cp4 = (const float4*)(P.cls[lvl] + (size_t)(b * N + k) * NCLS);
    float4 q = cp4[0];
    float v0 = q.x, v1 = q.y, v2 = q.z, v3 = q.w;
    int   c0 = 0,   c1 = 1,   c2 = 2,   c3 = 3;
    #pragma unroll
    for (int j = 1; j < 20; j++) {
        float4 p = cp4[j];
        if (p.x > v0) { v0 = p.x; c0 = 4*j;     }
        if (p.y > v1) { v1 = p.y; c1 = 4*j + 1; }
        if (p.z > v2) { v2 = p.z; c2 = 4*j + 2; }
        if (p.w > v3) { v3 = p.w; c3 = 4*j + 3; }
    }
    // combine: max value, lowest class among equal maxima
    float v = v0; int ci = c0;
    if (v1 > v || (v1 == v && c1 < ci)) { v = v1; ci = c1; }
    if (v2 > v || (v2 == v && c2 < ci)) { v = v2; ci = c2; }
    if (v3 > v || (v3 == v && c3 < ci)) { v = v3; ci = c3; }

    float ct    = P.ctr[lvl][(size_t)b * N + k];
    float score = sqrtf(sigm(v) * sigm(ct));

    const float4 r = ((const float4*)P.reg[lvl])[(size_t)b * N + k];
    float e0 = expf(r.x), e1 = expf(r.y), e2 = expf(r.z), e3 = expf(r.w);

    float px = ((k & ((1 << logW) - 1)) + 0.5f) * stride;
    float py = ((k >> logW)             + 0.5f) * stride;

    int x1 = (int)(px - e0);          // C truncation == jnp astype(int32)
    int y1 = (int)(py - e1);
    int x2 = (int)(px + e2);
    int y2 = (int)(py + e3);
    x1 = max(x1, 0);    y1 = max(y1, 0);
    x2 = min(x2, 1023); y2 = min(y2, 1023);

    float4 box = make_float4((float)x1, (float)y1, (float)x2, (float)y2);
    if (lvl < 3) {
        const int scrOff[3] = {0, 16384, 20480};
        size_t o = (size_t)b * SCR_STRIDE + scrOff[lvl] + k;
        g_scr_scores[o] = score;
        g_scr_class [o] = ci;
        g_scr_boxes [o] = box;
    } else {
        const int poolOff[2] = {3000, 3256};
        size_t o = (size_t)b * POOL + poolOff[lvl - 3] + k;
        g_pool_scores[o] = score;
        g_pool_class [o] = ci;
        g_pool_boxes [o] = box;
    }
}

// ---------------- kernel B: histogram radix-select top-1000 --------------------
#define TK_NT 1024
__global__ __launch_bounds__(TK_NT)
void topk_kernel()
{
    const int lvlN[3]    = {16384, 4096, 1024};
    const int lvlOff[3]  = {0, 16384, 20480};
    const int poolOff[3] = {0, 1000, 2000};

    int b = blockIdx.x / 3;
    int l = blockIdx.x % 3;
    int N = lvlN[l];
    size_t base  = (size_t)b * SCR_STRIDE + lvlOff[l];
    size_t pbase = (size_t)b * POOL + poolOff[l];

    extern __shared__ char tsm[];
    int* hist = (int*)tsm;                                          // 8192*4 = 32768
    unsigned long long* stash = (unsigned long long*)(tsm + 32768); // 4096*8 = 32768
    __shared__ int wsum[32], wsuf[32];
    __shared__ int s_B, s_above, s_w, s_t;
    __shared__ unsigned s_T;

    int tid = threadIdx.x, lane = tid & 31, wid = tid >> 5;

    for (int i = tid; i < 8192; i += TK_NT) hist[i] = 0;
    if (tid < 1000) g_pool_scores[pbase + tid] = NEGV;  // safety default
    if (tid == 0) { s_w = 0; s_t = 0; }
    __syncthreads();

    // pass 1: histogram of bits>>17 (scores in (0,1) -> bins < 8128)
    for (int i = tid; i < N; i += TK_NT) {
        unsigned u = __float_as_uint(g_scr_scores[base + i]);
        atomicAdd(&hist[u >> 17], 1);
    }
    __syncthreads();

    // block suffix scan over bins: find bin B with above(B) < 1000 <= above(B)+hist[B]
    int lo_bin = tid * 8;
    int psum = 0;
    #pragma unroll
    for (int j = 0; j < 8; j++) psum += hist[lo_bin + j];
    int x = psum;                                   // warp inclusive suffix scan
    #pragma unroll
    for (int off = 1; off < 32; off <<= 1) {
        int y = __shfl_down_sync(0xffffffffu, x, off);
        if (lane + off < 32) x += y;
    }
    if (lane == 0) wsum[wid] = x;
    __syncthreads();
    if (tid < 32) {
        int y = wsum[tid];
        #pragma unroll
        for (int off = 1; off < 32; off <<= 1) {
            int z = __shfl_down_sync(0xffffffffu, y, off);
            if (tid + off < 32) y += z;
        }
        wsuf[tid] = y;
    }
    __syncthreads();
    {
        int higher = (wid + 1 < 32) ? wsuf[wid + 1] : 0;
        int cum = higher + (x - psum);              // count in bins above this range
        #pragma unroll
        for (int j = 7; j >= 0; j--) {
            int h = hist[lo_bin + j];
            if (cum < 1000 && cum + h >= 1000) { s_B = lo_bin + j; s_above = cum; }
            cum += h;
        }
    }
    __syncthreads();
    int B = s_B, above = s_above;

    // pass 2: bins > B emit (shared-atomic slots); bin == B stashed
    for (int i = tid; i < N; i += TK_NT) {
        unsigned u = __float_as_uint(g_scr_scores[base + i]);
        int bin = (int)(u >> 17);
        if (bin > B) {
            int slot = atomicAdd(&s_w, 1);
            g_pool_scores[pbase + slot] = __uint_as_float(u);
            g_pool_class [pbase + slot] = g_scr_class[base + i];
            g_pool_boxes [pbase + slot] = g_scr_boxes[base + i];
        } else if (bin == B) {
            int p = atomicAdd(&s_t, 1);
            if (p < 4096) stash[p] = ((unsigned long long)u << 32) | (unsigned)i;
        }
    }
    __syncthreads();

    int M = min(s_t, 4096);
    int kneed = 1000 - above;                // how many needed from bin B

    // warp 0: 17-bit binary search within bin for threshold T
    if (wid == 0) {
        unsigned lo = (unsigned)B << 17, hi = ((unsigned)B << 17) | 0x1FFFFu;
        for (int it = 0; it < 17; it++) {
            unsigned d   = hi - lo;
            unsigned mid = lo + (d >> 1) + (d & 1u);    // ceil midpoint
            int loc = 0;
            for (int i = lane; i < M; i += 32) loc += ((unsigned)(stash[i] >> 32) >= mid);
            #pragma unroll
            for (int off = 16; off > 0; off >>= 1)
                loc += __shfl_xor_sync(0xffffffffu, loc, off);   // all lanes get total
            if (lo < hi) {
                if (loc >= kneed) lo = mid; else hi = mid - 1u;
            }
        }
        if (lane == 0) s_T = lo;
    }
    __syncthreads();
    unsigned T = s_T;

    // emit stash strictly greater than T
    for (int i = tid; i < M; i += TK_NT) {
        if ((unsigned)(stash[i] >> 32) > T) {
            int slot = atomicAdd(&s_w, 1);
            unsigned idx = (unsigned)(stash[i] & 0xffffffffull);
            g_pool_scores[pbase + slot] = __uint_as_float((unsigned)(stash[i] >> 32));
            g_pool_class [pbase + slot] = g_scr_class[base + idx];
            g_pool_boxes [pbase + slot] = g_scr_boxes[base + idx];
        }
    }
    __syncthreads();

    // ties == T: lowest original indices first (jax.lax.top_k tie semantics); tiny
    if (tid == 0) {
        int got  = s_w;
        int need = 1000 - got;
        for (int j = 0; j < need; j++) {
            unsigned bestIdx = 0xffffffffu; int bestPos = -1;
            for (int i = 0; i < M; i++) {
                unsigned long long e = stash[i];
                if ((unsigned)(e >> 32) == T) {
                    unsigned ii = (unsigned)(e & 0xffffffffull);
                    if (ii < bestIdx) { bestIdx = ii; bestPos = i; }
                }
            }
            if (bestPos < 0) break;
            stash[bestPos] = 0;                    // consume
            int slot = got + j;
            g_pool_scores[pbase + slot] = __uint_as_float(T);
            g_pool_class [pbase + slot] = g_scr_class[base + bestIdx];
            g_pool_boxes [pbase + slot] = g_scr_boxes[base + bestIdx];
        }
    }
}

// ---------------- kernel C: sort + scan-kept NMS, one block per image ----------
#define NMS_NT 1024
__global__ __launch_bounds__(NMS_NT)
void nms_kernel(float* __restrict__ out)
{
    int b = blockIdx.x;
    extern __shared__ char dsm[];
    unsigned long long* key = (unsigned long long*)dsm;   // 4096*8 = 32768
    short* sx1  = (short*)(dsm + 32768);                  // 3328*2 each
    short* sy1  = (short*)(dsm + 32768 + 6656);
    short* sx2  = (short*)(dsm + 32768 + 13312);
    short* sy2  = (short*)(dsm + 32768 + 19968);
    short* scls = (short*)(dsm + 32768 + 26624);          // -> 66048
    float* ssc  = (float*)(dsm + 66048);                  // 3328*4 -> 79360
    float* kx1  = (float*)(dsm + 79360);                  // kept arrays: 7*100 floats
    float* ky1  = kx1 + 100;
    float* kx2  = kx1 + 200;
    float* ky2  = kx1 + 300;
    float* kar  = kx1 + 400;
    float* ksc  = kx1 + 500;
    float* kcl  = kx1 + 600;                              // end 82160

    int tid = threadIdx.x, lane = tid & 31;

    // keys: (score_bits << 32) | ~pool_index ; dead -> 0
    for (int i = tid; i < NPAD; i += NMS_NT) {
        unsigned long long k = 0ull;
        if (i < POOL) {
            float sc = g_pool_scores[(size_t)b * POOL + i];
            if (sc > MIN_SCORE)
                k = ((unsigned long long)__float_as_uint(sc) << 32) | (unsigned)(~i);
        }
        key[i] = k;
    }

    // bitonic sort descending (score desc, pool index asc on equal scores)
    for (int kk = 2; kk <= NPAD; kk <<= 1) {
        for (int jj = kk >> 1; jj > 0; jj >>= 1) {
            __syncthreads();
            for (int t = tid; t < NPAD; t += NMS_NT) {
                int ixj = t ^ jj;
                if (ixj > t) {
                    unsigned long long a = key[t], c = key[ixj];
                    bool up = ((t & kk) == 0);
                    if ((a < c) == up) { key[t] = c; key[ixj] = a; }
                }
            }
        }
    }
    __syncthreads();

    // gather sorted candidates
    for (int i = tid; i < POOL; i += NMS_NT) {
        unsigned long long k = key[i];
        if (k) {
            unsigned idx = ~(unsigned)(k & 0xffffffffull);
            ssc[i] = __uint_as_float((unsigned)(k >> 32));
            float4 f = g_pool_boxes[(size_t)b * POOL + idx];
            sx1[i] = (short)f.x; sy1[i] = (short)f.y;
            sx2[i] = (short)f.z; sy2[i] = (short)f.w;
            scls[i] = (short)g_pool_class[(size_t)b * POOL + idx];
        } else {
            ssc[i] = 0.f;
        }
    }
    __syncthreads();

    // scan-kept greedy NMS: warp 0 only, broadcasts via shared + __syncwarp.
    // Equivalence: greedy argmax-NMS == scan sorted order, keep iff
    // IoU <= thr vs every previously-kept box (only kept boxes suppress).
    if (tid < 32) {
        int kept = 0;
        for (int base0 = 0; base0 < POOL && kept < 100; base0 += 32) {
            if (ssc[base0] <= 0.f) break;          // sorted: all dead from here
            int i = base0 + lane;
            bool alive = (i < POOL) && (ssc[i] > 0.f);
            float x1 = 0, y1 = 0, x2 = 0, y2 = 0, a = 0;
            if (alive) {
                x1 = sx1[i]; y1 = sy1[i]; x2 = sx2[i]; y2 = sy2[i];
                a = (x2 - x1) * (y2 - y1);
                #pragma unroll 1
                for (int k = 0; k < kept && alive; k++) {
                    float iw = fmaxf(fminf(x2, kx2[k]) - fmaxf(x1, kx1[k]), 0.f);
                    float ih = fmaxf(fminf(y2, ky2[k]) - fmaxf(y1, ky1[k]), 0.f);
                    float inter = iw * ih;
                    float denom = ((a + kar[k]) - inter) + 1e-12f;  // same assoc as ref
                    if (inter / denom > NMS_THR) alive = false;
                }
            }
            unsigned m = __ballot_sync(0xffffffffu, alive);
            while (m != 0u && kept < 100) {
                int sl = __ffs(m) - 1;
                if (lane == sl) {
                    kx1[kept] = x1; ky1[kept] = y1;
                    kx2[kept] = x2; ky2[kept] = y2;
                    kar[kept] = a;
                    ksc[kept] = ssc[i];
                    kcl[kept] = (float)scls[i];
                    alive = false;
                }
                __syncwarp();
                float rx1 = kx1[kept], ry1 = ky1[kept];
                float rx2 = kx2[kept], ry2 = ky2[kept], ra = kar[kept];
                kept++;
                if (alive && lane > sl) {
                    float iw = fmaxf(fminf(x2, rx2) - fmaxf(x1, rx1), 0.f);
                    float ih = fmaxf(fminf(y2, ry2) - fmaxf(y1, ry1), 0.f);
                    float inter = iw * ih;
                    float denom = ((a + ra) - inter) + 1e-12f;
                    if (inter / denom > NMS_THR) alive = false;
                }
                m = __ballot_sync(0xffffffffu, alive);
            }
        }
        // warp 0 owns ALL output writes (no cross-warp race)
        for (int j = lane; j < 100; j += 32) {
            bool ok = j < kept;
            out[b * 100 + j]       = ok ? ksc[j] : -1.f;
            out[800 + b * 100 + j] = ok ? kcl[j] : -1.f;
            float* ob = out + 1600 + ((size_t)(b * 100 + j)) * 4;
            if (ok) { ob[0] = kx1[j]; ob[1] = ky1[j]; ob[2] = kx2[j]; ob[3] = ky2[j]; }
            else    { ob[0] = ob[1] = ob[2] = ob[3] = -1.f; }
        }
    }
}

// ---------------- host launcher -------------------------------------------------
extern "C" void kernel_launch(void* const* d_in, const int* in_sizes, int n_in,
                              void* d_out, int out_size)
{
    (void)n_in; (void)out_size;

    HeadPtrs P;
    if (in_sizes[1] == 8 * 64 * 64 * NCLS) {
        for (int i = 0; i < 5; i++) {
            P.cls[i] = (const float*)d_in[i];
            P.reg[i] = (const float*)d_in[5 + i];
            P.ctr[i] = (const float*)d_in[10 + i];
        }
    } else {
        for (int i = 0; i < 5; i++) {
            P.cls[i] = (const float*)d_in[3 * i + 0];
            P.reg[i] = (const float*)d_in[3 * i + 1];
            P.ctr[i] = (const float*)d_in[3 * i + 2];
        }
    }

    decode_all_kernel<<<(TOTAL_LOCS + 255) / 256, 256>>>(P);

    cudaFuncSetAttribute(topk_kernel, cudaFuncAttributeMaxDynamicSharedMemorySize, 65536);
    topk_kernel<<<24, TK_NT, 65536>>>();

    cudaFuncSetAttribute(nms_kernel, cudaFuncAttributeMaxDynamicSharedMemorySize, 82176);
    nms_kernel<<<BATCH, NMS_NT, 82176>>>((float*)d_out);
}